// round 6
// baseline (speedup 1.0000x reference)
#include <cuda_runtime.h>
#include <math.h>

#define Bn 32
#define Sn 512
#define Hn 768
#define FDn 64
#define Pn 30
#define NROWS (Bn*Sn)    // 16384
#define KSn 2

typedef unsigned long long u64;

__device__ __forceinline__ void fma2(u64 &d, u64 a, u64 b) {
    asm("fma.rn.f32x2 %0, %1, %2, %0;" : "+l"(d) : "l"(a), "l"(b));
}
__device__ __forceinline__ void add2(u64 &d, u64 a) {
    asm("add.rn.f32x2 %0, %0, %1;" : "+l"(d) : "l"(a));
}
__device__ __forceinline__ u64 rep2(float a) {
    u64 r; asm("mov.b64 %0, {%1, %1};" : "=l"(r) : "f"(a)); return r;
}
__device__ __forceinline__ float2 unpk(u64 v) {
    float2 f; asm("mov.b64 {%0, %1}, %2;" : "=f"(f.x), "=f"(f.y) : "l"(v)); return f;
}

// ------------------ scratch ------------------
__device__ float g_pt [KSn * NROWS * 32];   // 4.2 MB text partials [ks][row][p]
__device__ float g_textT [Bn * 32 * Sn];    // [b][p][s]
__device__ float g_audioT[Bn * 32 * Sn];
__device__ float g_part[128];
__device__ float g_raw0[Bn * Sn];
__device__ float g_avp[Bn * 16 * Hn];

// ================= K1: text projection (K-split 2, 8x8 micro, f32x2) =================
// grid (64 rowblocks, 2 ksplit), block 128 = 32 rthr x 4 pthr
__global__ __launch_bounds__(128, 1) void k_proj(const float* __restrict__ hs,
                                                 const float* __restrict__ Wt) {
    __shared__ __align__(16) float sA[256 * 36];   // [r][k] chunk 32k, pitch 36
    __shared__ __align__(16) float sW[32 * 32];    // [k][p]
    int tid = threadIdx.x;
    int rthr = tid >> 2, pthr = tid & 3;
    int row0 = blockIdx.x * 256;
    int kbase = blockIdx.y * 384;
    const float4* hs4 = (const float4*)hs;
    const float4* Wt4 = (const float4*)Wt;

    u64 acc[8][4];
    #pragma unroll
    for (int i = 0; i < 8; i++)
        #pragma unroll
        for (int j = 0; j < 4; j++) acc[i][j] = 0ull;

    for (int cc = 0; cc < 12; cc++) {
        int kb = kbase + cc * 32;
        __syncthreads();
        #pragma unroll
        for (int q = 0; q < 16; q++) {          // A: 256 x 32 = 2048 float4
            int e = tid + 128 * q;
            int r = e >> 3, c = e & 7;
            float4 v = hs4[(size_t)(row0 + r) * 192 + (kb >> 2) + c];
            *(float4*)&sA[r * 36 + c * 4] = v;
        }
        // W^T gather: 30 p x 8 float4 (L2-resident)
        #pragma unroll
        for (int idx = tid; idx < 240; idx += 128) {
            int p = idx >> 3, k4 = idx & 7;
            float4 v = Wt4[p * 192 + (kb >> 2) + k4];
            sW[(k4 * 4 + 0) * 32 + p] = v.x;
            sW[(k4 * 4 + 1) * 32 + p] = v.y;
            sW[(k4 * 4 + 2) * 32 + p] = v.z;
            sW[(k4 * 4 + 3) * 32 + p] = v.w;
        }
        if (tid < 64) sW[(tid >> 1) * 32 + 30 + (tid & 1)] = 0.f;
        __syncthreads();

        #pragma unroll
        for (int k4 = 0; k4 < 8; k4++) {
            float4 a4[8];
            #pragma unroll
            for (int i = 0; i < 8; i++)
                a4[i] = *(const float4*)&sA[(rthr + 32 * i) * 36 + k4 * 4];
            #pragma unroll
            for (int kk = 0; kk < 4; kk++) {
                const u64* wp = (const u64*)&sW[(k4 * 4 + kk) * 32 + pthr * 8];
                u64 w0 = wp[0], w1 = wp[1], w2 = wp[2], w3 = wp[3];
                #pragma unroll
                for (int i = 0; i < 8; i++) {
                    float av = (kk == 0) ? a4[i].x : (kk == 1) ? a4[i].y :
                               (kk == 2) ? a4[i].z : a4[i].w;
                    u64 a = rep2(av);
                    fma2(acc[i][0], a, w0); fma2(acc[i][1], a, w1);
                    fma2(acc[i][2], a, w2); fma2(acc[i][3], a, w3);
                }
            }
        }
    }
    #pragma unroll
    for (int i = 0; i < 8; i++) {
        u64* d = (u64*)&g_pt[(size_t)blockIdx.y * (NROWS * 32) +
                             (size_t)(row0 + rthr + 32 * i) * 32 + pthr * 8];
        d[0] = acc[i][0]; d[1] = acc[i][1]; d[2] = acc[i][2]; d[3] = acc[i][3];
    }
}

// ================= K2: finalize (merge partials + audio GEMM + transpose) =================
// grid 128 (128-row tiles), block 128 = 32 rthr x 4 pthr
__global__ __launch_bounds__(128) void k_fin(const float* __restrict__ ad,
                                             const float* __restrict__ Wa) {
    __shared__ __align__(16) float sbuf[128 * 68 + 64 * 32];
    __shared__ float red[128];
    float* sAa = sbuf;                // 128 x 64, pitch 68
    float* sWa = sbuf + 128 * 68;     // 64 x 32
    float* sX  = sbuf;                // 32 x 129 alias

    int tid = threadIdx.x;
    int rthr = tid >> 2, pthr = tid & 3;
    int row0 = blockIdx.x * 128;
    int b = row0 >> 9, sbase = row0 & 511;

    #pragma unroll
    for (int q = 0; q < 16; q++) {
        int e = tid + 128 * q;
        int r = e >> 4, c = e & 15;
        float4 v = ((const float4*)ad)[(size_t)(row0 + r) * 16 + c];
        *(float4*)&sAa[r * 68 + c * 4] = v;
    }
    // Wa^T gather: 30 p x 16 float4
    #pragma unroll
    for (int idx = tid; idx < 480; idx += 128) {
        int p = idx >> 4, k4 = idx & 15;
        float4 v = ((const float4*)Wa)[p * 16 + k4];
        sWa[(k4 * 4 + 0) * 32 + p] = v.x;
        sWa[(k4 * 4 + 1) * 32 + p] = v.y;
        sWa[(k4 * 4 + 2) * 32 + p] = v.z;
        sWa[(k4 * 4 + 3) * 32 + p] = v.w;
    }
    { int k = tid >> 1; sWa[k * 32 + 30 + (tid & 1)] = 0.f; }   // FIXED: k covers 0..63
    __syncthreads();

    u64 aacc[4][4];
    #pragma unroll
    for (int i = 0; i < 4; i++)
        #pragma unroll
        for (int j = 0; j < 4; j++) aacc[i][j] = 0ull;
    #pragma unroll 8
    for (int k = 0; k < 64; k++) {
        u64 w[4];
        #pragma unroll
        for (int j = 0; j < 4; j++)
            w[j] = *(const u64*)&sWa[k * 32 + pthr * 8 + 2 * j];
        #pragma unroll
        for (int i = 0; i < 4; i++) {
            u64 a = rep2(sAa[(rthr * 4 + i) * 68 + k]);
            fma2(aacc[i][0], a, w[0]); fma2(aacc[i][1], a, w[1]);
            fma2(aacc[i][2], a, w[2]); fma2(aacc[i][3], a, w[3]);
        }
    }

    u64 tacc[4][4];
    #pragma unroll
    for (int i = 0; i < 4; i++) {
        size_t base = (size_t)(row0 + rthr * 4 + i) * 32 + pthr * 8;
        #pragma unroll
        for (int j = 0; j < 4; j++) tacc[i][j] = 0ull;
        #pragma unroll
        for (int ks = 0; ks < KSn; ks++) {
            const u64* s = (const u64*)&g_pt[(size_t)ks * (NROWS * 32) + base];
            add2(tacc[i][0], s[0]); add2(tacc[i][1], s[1]);
            add2(tacc[i][2], s[2]); add2(tacc[i][3], s[3]);
        }
    }

    float sumsq = 0.f;
    #pragma unroll
    for (int i = 0; i < 4; i++)
        #pragma unroll
        for (int j = 0; j < 4; j++) {
            float2 f = unpk(tacc[i][j]);
            sumsq += f.x * f.x + f.y * f.y;
        }
    red[tid] = sumsq;
    __syncthreads();

    // transpose text
    #pragma unroll
    for (int i = 0; i < 4; i++)
        #pragma unroll
        for (int j = 0; j < 4; j++) {
            float2 f = unpk(tacc[i][j]);
            int s = rthr * 4 + i;
            sX[(pthr * 8 + 2 * j)     * 129 + s] = f.x;
            sX[(pthr * 8 + 2 * j + 1) * 129 + s] = f.y;
        }
    __syncthreads();
    #pragma unroll
    for (int q = 0; q < 32; q++) {
        int e = tid + 128 * q;
        int p = e >> 7, c = e & 127;
        g_textT[(size_t)(b * 32 + p) * 512 + sbase + c] = sX[p * 129 + c];
    }
    __syncthreads();
    // transpose audio
    #pragma unroll
    for (int i = 0; i < 4; i++)
        #pragma unroll
        for (int j = 0; j < 4; j++) {
            float2 f = unpk(aacc[i][j]);
            int s = rthr * 4 + i;
            sX[(pthr * 8 + 2 * j)     * 129 + s] = f.x;
            sX[(pthr * 8 + 2 * j + 1) * 129 + s] = f.y;
        }
    __syncthreads();
    #pragma unroll
    for (int q = 0; q < 32; q++) {
        int e = tid + 128 * q;
        int p = e >> 7, c = e & 127;
        g_audioT[(size_t)(b * 32 + p) * 512 + sbase + c] = sX[p * 129 + c];
    }

    __syncthreads();
    for (int s = 64; s > 0; s >>= 1) {
        if (tid < s) red[tid] += red[tid + s];
        __syncthreads();
    }
    if (tid == 0) g_part[blockIdx.x] = red[0];
}

// ================= K3: scores (warp-spec compute, all-thread stores) =================
// grid (36 tri-tiles, 32 b), block 256
__global__ __launch_bounds__(256) void k_scores(const float* __restrict__ twp,
                                                const float* __restrict__ awp,
                                                const float* __restrict__ fbp,
                                                float* __restrict__ out_ta,
                                                float* __restrict__ out_fa) {
    __shared__ __align__(16) float T[8336];
    // compute: Ts@0, Tt@2048, As@4096, At@6144 (32p x 64)
    // epilogue: xT@0 (64s x 65), xA@4160
    float* xT = T;
    float* xA = T + 4160;

    int x = blockIdx.x, si = 0;
    while (x >= 8 - si) { x -= 8 - si; si++; }
    int ti = si + x;
    int b = blockIdx.y;
    int s0 = si * 64, t0 = ti * 64;
    int tid = threadIdx.x;

    // norm scale prologue
    if (tid < 32) {
        float v = g_part[tid] + g_part[tid + 32] + g_part[tid + 64] + g_part[tid + 96];
        #pragma unroll
        for (int o = 16; o > 0; o >>= 1) v += __shfl_xor_sync(0xffffffff, v, o);
        if (tid == 0) T[8320] = rsqrtf(v);
    }

    const float4* gT = (const float4*)(g_textT  + (size_t)b * 16384);
    const float4* gA = (const float4*)(g_audioT + (size_t)b * 16384);
    #pragma unroll
    for (int q = 0; q < 8; q++) {
        int e = tid + 256 * q;
        int tile = e >> 9, id2 = e & 511;
        int p = id2 >> 4, c = id2 & 15;
        const float4* src = (tile < 2) ? gT : gA;
        int off = (tile & 1) ? (t0 >> 2) : (s0 >> 2);
        ((float4*)T)[tile * 512 + p * 16 + c] = src[p * 128 + off + c];
    }
    __syncthreads();
    float cs = T[8320];

    int m = tid >> 7;                 // 0 text, 1 audio
    int half = tid & 127;
    int sthr = half >> 3, tthr = half & 7;
    const float* sS = T + m * 4096;
    const float* sT = sS + 2048;

    u64 acc[4][4];
    #pragma unroll
    for (int i = 0; i < 4; i++)
        #pragma unroll
        for (int j = 0; j < 4; j++) acc[i][j] = 0ull;

    #pragma unroll 5
    for (int p = 0; p < Pn; p++) {
        const float* ps = sS + p * 64 + sthr * 4;
        const float* pt = sT + p * 64 + tthr * 8;
        u64 b0 = *(const u64*)(pt);
        u64 b1 = *(const u64*)(pt + 2);
        u64 b2 = *(const u64*)(pt + 4);
        u64 b3 = *(const u64*)(pt + 6);
        #pragma unroll
        for (int i = 0; i < 4; i++) {
            u64 a = rep2(ps[i]);
            fma2(acc[i][0], a, b0); fma2(acc[i][1], a, b1);
            fma2(acc[i][2], a, b2); fma2(acc[i][3], a, b3);
        }
    }
    __syncthreads();

    // stage results to smem (text scaled+relu, audio relu)
    float* dst = m ? xA : xT;
    float mult = m ? 1.f : cs;
    #pragma unroll
    for (int i = 0; i < 4; i++) {
        float* row = dst + (sthr * 4 + i) * 65 + tthr * 8;
        #pragma unroll
        for (int j = 0; j < 4; j++) {
            float2 f = unpk(acc[i][j]);
            row[2 * j]     = fmaxf(f.x * mult, 0.f);
            row[2 * j + 1] = fmaxf(f.y * mult, 0.f);
        }
    }
    __syncthreads();

    float tw = twp[0], aw = awp[0], fb = fbp[0];

    // normal stores [s][t] — all 256 threads
    #pragma unroll
    for (int g = 0; g < 4; g++) {
        int f4id = tid + 256 * g;
        int s = f4id >> 4, tq = f4id & 15;
        const float* pT = xT + s * 65 + tq * 4;
        const float* pA = xA + s * 65 + tq * 4;
        float ta[4], fa[4], rw[4];
        #pragma unroll
        for (int j = 0; j < 4; j++) {
            float t_ = pT[j], a_ = pA[j];
            float r_ = tw * t_ + aw * a_ + fb;
            ta[j] = t_; rw[j] = r_; fa[j] = fmaxf(r_, 0.f);
        }
        size_t base = ((size_t)(b * Sn + s0 + s)) * Sn + t0 + tq * 4;
        *(float4*)(out_ta + base) = make_float4(ta[0], ta[1], ta[2], ta[3]);
        *(float4*)(out_fa + base) = make_float4(fa[0], fa[1], fa[2], fa[3]);
        if (si == 0 && s == 0)
            *(float4*)(g_raw0 + b * Sn + t0 + tq * 4) =
                make_float4(rw[0], rw[1], rw[2], rw[3]);
    }

    // mirror stores [t][s]
    if (si != ti) {
        #pragma unroll
        for (int g = 0; g < 4; g++) {
            int f4id = tid + 256 * g;
            int t = f4id >> 4, sq = f4id & 15;
            float ta[4], fa[4];
            #pragma unroll
            for (int j = 0; j < 4; j++) {
                float t_ = xT[(sq * 4 + j) * 65 + t];
                float a_ = xA[(sq * 4 + j) * 65 + t];
                ta[j] = t_;
                fa[j] = fmaxf(tw * t_ + aw * a_ + fb, 0.f);
            }
            size_t base = ((size_t)(b * Sn + t0 + t)) * Sn + s0 + sq * 4;
            *(float4*)(out_ta + base) = make_float4(ta[0], ta[1], ta[2], ta[3]);
            *(float4*)(out_fa + base) = make_float4(fa[0], fa[1], fa[2], fa[3]);
        }
    }
}

// ================= K4: softmax + AV partials =================
// grid (32 b, 16 t-chunks), 256 threads
__global__ __launch_bounds__(256) void k_softav(const float* __restrict__ hs,
                                                const float* __restrict__ am) {
    __shared__ float sp[Sn];
    __shared__ float red[256];
    int b = blockIdx.x, cy = blockIdx.y, tid = threadIdx.x;
    int t0c = cy * 32;

    float mbase = am[b * Sn];
    float l0 = g_raw0[b * Sn + tid]       + am[b * Sn + tid]       + mbase;
    float l1 = g_raw0[b * Sn + tid + 256] + am[b * Sn + tid + 256] + mbase;
    red[tid] = fmaxf(l0, l1);
    __syncthreads();
    for (int s = 128; s > 0; s >>= 1) {
        if (tid < s) red[tid] = fmaxf(red[tid], red[tid + s]);
        __syncthreads();
    }
    float mx = red[0];
    __syncthreads();
    float e0 = expf(l0 - mx), e1 = expf(l1 - mx);
    red[tid] = e0 + e1;
    __syncthreads();
    for (int s = 128; s > 0; s >>= 1) {
        if (tid < s) red[tid] += red[tid + s];
        __syncthreads();
    }
    float inv = 1.f / red[0];
    __syncthreads();
    sp[tid] = e0 * inv; sp[tid + 256] = e1 * inv;
    __syncthreads();

    if (tid < 192) {
        const float4* hb = (const float4*)(hs + (size_t)b * Sn * Hn);
        float4 acc = make_float4(0.f, 0.f, 0.f, 0.f);
        #pragma unroll 8
        for (int t = 0; t < 32; t++) {
            float p = sp[t0c + t];
            float4 h = hb[(size_t)(t0c + t) * 192 + tid];
            acc.x += p * h.x; acc.y += p * h.y; acc.z += p * h.z; acc.w += p * h.w;
        }
        ((float4*)g_avp)[(size_t)(b * 16 + cy) * 192 + tid] = acc;
    }
}

// ================= K5: dense GEMV + layernorm fused =================
// grid 32 (one block per batch), 256 threads
__global__ __launch_bounds__(256) void k_denseln(const float* __restrict__ hs,
                                                 const float* __restrict__ Wd,
                                                 const float* __restrict__ bd,
                                                 const float* __restrict__ lw,
                                                 const float* __restrict__ lb,
                                                 float* __restrict__ out0) {
    __shared__ float sx[Hn];
    __shared__ float sh[Hn];
    __shared__ float red[256];
    int b = blockIdx.x, tid = threadIdx.x;
    int w = tid >> 5, lane = tid & 31;

    for (int i = tid; i < Hn; i += 256) {
        float v = hs[(size_t)b * Sn * Hn + i];
        #pragma unroll
        for (int c = 0; c < 16; c++) v += g_avp[(size_t)(b * 16 + c) * Hn + i];
        sx[i] = v;
    }
    __syncthreads();

    const float4* sx4 = (const float4*)sx;
    for (int q = 0; q < 96; q++) {
        int o = w * 96 + q;
        const float4* w4 = (const float4*)(Wd + (size_t)o * Hn);
        float acc = 0.f;
        #pragma unroll
        for (int c = 0; c < 6; c++) {
            float4 wv = w4[c * 32 + lane];
            float4 xv = sx4[c * 32 + lane];
            acc += wv.x * xv.x + wv.y * xv.y + wv.z * xv.z + wv.w * xv.w;
        }
        #pragma unroll
        for (int s = 16; s > 0; s >>= 1)
            acc += __shfl_down_sync(0xffffffff, acc, s);
        if (lane == 0) sh[o] = acc + bd[o];
    }
    __syncthreads();

    float hv[3];
    #pragma unroll
    for (int j = 0; j < 3; j++) hv[j] = sh[tid + 256 * j];
    red[tid] = hv[0] + hv[1] + hv[2];
    __syncthreads();
    for (int s = 128; s > 0; s >>= 1) {
        if (tid < s) red[tid] += red[tid + s];
        __syncthreads();
    }
    float u = red[0] / (float)Hn;
    __syncthreads();
    float vs = 0.f;
    #pragma unroll
    for (int j = 0; j < 3; j++) { float d = hv[j] - u; vs += d * d; }
    red[tid] = vs;
    __syncthreads();
    for (int s = 128; s > 0; s >>= 1) {
        if (tid < s) red[tid] += red[tid + s];
        __syncthreads();
    }
    float rstd = rsqrtf(red[0] / (float)Hn + 1e-12f);
    #pragma unroll
    for (int j = 0; j < 3; j++) {
        int o = tid + 256 * j;
        out0[b * Hn + o] = lw[o] * (hv[j] - u) * rstd + lb[o];
    }
}

// ------------------ launch ------------------
extern "C" void kernel_launch(void* const* d_in, const int* in_sizes, int n_in,
                              void* d_out, int out_size) {
    const float* hs = (const float*)d_in[0];
    const float* ad = (const float*)d_in[1];
    const float* am = (const float*)d_in[2];
    const float* Wt = (const float*)d_in[3];
    const float* Wa = (const float*)d_in[4];
    const float* tw = (const float*)d_in[5];
    const float* aw = (const float*)d_in[6];
    const float* fb = (const float*)d_in[7];
    const float* Wd = (const float*)d_in[8];
    const float* bd = (const float*)d_in[9];
    const float* lw = (const float*)d_in[10];
    const float* lb = (const float*)d_in[11];

    float* out    = (float*)d_out;
    float* out_h0 = out;
    float* out_ta = out + Bn * Hn;
    float* out_fa = out + Bn * Hn + (size_t)Bn * Sn * Sn;

    k_proj<<<dim3(64, 2), 128>>>(hs, Wt);
    k_fin<<<128, 128>>>(ad, Wa);
    k_scores<<<dim3(36, 32), 256>>>(tw, aw, fb, out_ta, out_fa);
    k_softav<<<dim3(32, 16), 256>>>(hs, am);
    k_denseln<<<32, 256>>>(hs, Wd, bd, lw, lb, out_h0);
}